// round 1
// baseline (speedup 1.0000x reference)
#include <cuda_runtime.h>
#include <math.h>

// ---------------- problem constants ----------------
#define Nn   10000
#define Bb   8
#define Tt   12
#define Ff   8
#define Hh   64
#define Ee   320000
#define HOR  12
#define Mm   (Bb*Nn)          // 80000 rows
#define KCAT 320              // 5*H
#define CDEC 96               // F*HOR

// ---------------- scratch (__device__ globals; no cudaMalloc) ----------------
__device__ float g_h0[Mm*Hh];
__device__ float g_h1[Mm*Hh];
__device__ float g_z0[Mm*Hh];   // fwd hop1
__device__ float g_z1[Mm*Hh];   // fwd hop2
__device__ float g_z2[Mm*Hh];   // bwd hop1
__device__ float g_z3[Mm*Hh];   // bwd hop2
__device__ int   g_src[Ee], g_tgt[Ee];
__device__ int   g_rowptr_f[Nn+1], g_rowptr_b[Nn+1];
__device__ int   g_cnt_f[Nn], g_cnt_b[Nn], g_cur_f[Nn], g_cur_b[Nn];
__device__ float g_deg_f[Nn], g_deg_b[Nn];
__device__ int   g_adjn_f[Ee]; __device__ float g_adjw_f[Ee];
__device__ int   g_adjn_b[Ee]; __device__ float g_adjw_b[Ee];
__device__ float g_W2[KCAT*CDEC];
__device__ float g_b2[CDEC];
__device__ int   g_flag64;

// ---------------- edge dtype detection ----------------
__global__ void k_detect(const unsigned int* ei_raw) {
    // int64 little-endian node ids < 2^31 => every odd 32-bit word is 0
    bool all0 = true;
    for (int i = 0; i < 16; i++)
        if (ei_raw[2*i + 1] != 0u) all0 = false;
    g_flag64 = all0 ? 1 : 0;
}

__global__ void k_convert(const void* ei) {
    int e = blockIdx.x * blockDim.x + threadIdx.x;
    if (e >= Ee) return;
    if (g_flag64) {
        const long long* p = (const long long*)ei;
        g_src[e] = (int)p[e];
        g_tgt[e] = (int)p[Ee + e];
    } else {
        const int* p = (const int*)ei;
        g_src[e] = p[e];
        g_tgt[e] = p[Ee + e];
    }
}

// ---------------- zero init ----------------
__global__ void k_zero() {
    int stride = gridDim.x * blockDim.x;
    for (int i = blockIdx.x * blockDim.x + threadIdx.x; i < Mm*Hh; i += stride) {
        g_h0[i] = 0.f;
        if (i < Nn) {
            g_cnt_f[i] = 0; g_cnt_b[i] = 0;
            g_cur_f[i] = 0; g_cur_b[i] = 0;
            g_deg_f[i] = 0.f; g_deg_b[i] = 0.f;
        }
    }
}

// ---------------- CSR build ----------------
__global__ void k_count(const float* __restrict__ ew) {
    int e = blockIdx.x * blockDim.x + threadIdx.x;
    if (e >= Ee) return;
    int s = g_src[e], t = g_tgt[e];
    float w = ew[e];
    atomicAdd(&g_cnt_f[t], 1);  atomicAdd(&g_deg_f[t], w);
    atomicAdd(&g_cnt_b[s], 1);  atomicAdd(&g_deg_b[s], w);
}

__global__ void k_scan() {
    __shared__ int sbuf[1024];
    __shared__ int sOff;
    int tid = threadIdx.x;
    for (int which = 0; which < 2; ++which) {
        const int* cnt = which ? g_cnt_b : g_cnt_f;
        int* rp        = which ? g_rowptr_b : g_rowptr_f;
        if (tid == 0) { sOff = 0; rp[0] = 0; }
        __syncthreads();
        for (int base = 0; base < Nn; base += 1024) {
            int i = base + tid;
            int v = (i < Nn) ? cnt[i] : 0;
            sbuf[tid] = v;
            __syncthreads();
            for (int d = 1; d < 1024; d <<= 1) {
                int add = (tid >= d) ? sbuf[tid - d] : 0;
                __syncthreads();
                sbuf[tid] += add;
                __syncthreads();
            }
            if (i < Nn) rp[i + 1] = sOff + sbuf[tid];
            __syncthreads();
            if (tid == 0) sOff += sbuf[1023];
            __syncthreads();
        }
        __syncthreads();
    }
}

__global__ void k_fill(const float* __restrict__ ew) {
    int e = blockIdx.x * blockDim.x + threadIdx.x;
    if (e >= Ee) return;
    int s = g_src[e], t = g_tgt[e];
    float w = ew[e];
    float df = g_deg_f[t]; df = (df == 0.f) ? 1.f : df;
    int pf = g_rowptr_f[t] + atomicAdd(&g_cur_f[t], 1);
    g_adjn_f[pf] = s;  g_adjw_f[pf] = w / df;
    float db = g_deg_b[s]; db = (db == 0.f) ? 1.f : db;
    int pb = g_rowptr_b[s] + atomicAdd(&g_cur_b[s], 1);
    g_adjn_b[pb] = t;  g_adjw_b[pb] = w / db;
}

// ---------------- W2 = filt_W @ dec_W ; b2 = filt_b @ dec_W + dec_b ----------------
__global__ void k_w2(const float* __restrict__ filtW, const float* __restrict__ filtB,
                     const float* __restrict__ decW,  const float* __restrict__ decB) {
    int c = threadIdx.x;   // 0..95
    int k = blockIdx.x;    // 0..320
    if (k < KCAT) {
        float acc = 0.f;
        for (int j = 0; j < Hh; j++) acc += filtW[k*Hh + j] * decW[j*CDEC + c];
        g_W2[k*CDEC + c] = acc;
    } else {
        float acc = decB[c];
        for (int j = 0; j < Hh; j++) acc += filtB[j] * decW[j*CDEC + c];
        g_b2[c] = acc;
    }
}

// ---------------- fused encoder + GRU step ----------------
// One block = 64 rows. smem: WihT[64][193], WhhT[64][193], Xe[64][65](k-major),
// H[64][65](k-major), xrow[64][8], encW[8][64]. 136192 bytes.
#define GRU_SMEM ((2*64*193 + 2*64*65 + 64*8 + 8*64) * 4)

__global__ __launch_bounds__(256, 1)
void k_gru(const float* __restrict__ x,
           const float* __restrict__ encW, const float* __restrict__ encB,
           const float* __restrict__ nodeEmb,
           const float* __restrict__ Wih, const float* __restrict__ Whh,
           const float* __restrict__ bih, const float* __restrict__ bhh,
           int t)
{
    extern __shared__ float sm[];
    float* sWih = sm;                    // 64*193
    float* sWhh = sWih + 64*193;
    float* sXe  = sWhh + 64*193;         // [k][row] 64*65
    float* sH   = sXe  + 64*65;
    float* sXr  = sH   + 64*65;          // [row][8]
    float* sEw  = sXr  + 64*8;           // [8][64]

    const float* hin = (t & 1) ? g_h1 : g_h0;
    float*       hout= (t & 1) ? g_h0 : g_h1;

    int tid = threadIdx.x;
    int m0  = blockIdx.x * 64;

    // phase 1: x rows + encoder weights
    for (int idx = tid; idx < 8*64; idx += 256) sEw[idx] = encW[idx];
    for (int idx = tid; idx < 64*8; idx += 256) {
        int r = idx >> 3, f = idx & 7;
        int m = m0 + r, b = m / Nn, n = m - b * Nn;
        sXr[idx] = x[((b * Tt + t) * Nn + n) * Ff + f];
    }
    __syncthreads();

    // phase 2: weights (transposed, padded), h tile, encoded x tile
    for (int idx = tid; idx < 192*64; idx += 256) {
        int g = idx >> 6, k = idx & 63;
        sWih[k*193 + g] = Wih[idx];
        sWhh[k*193 + g] = Whh[idx];
    }
    for (int idx = tid; idx < 64*64; idx += 256) {
        int r = idx >> 6, k = idx & 63;
        sH[k*65 + r] = hin[(m0 + r) * Hh + k];
    }
    for (int idx = tid; idx < 64*64; idx += 256) {
        int r = idx >> 6, hh = idx & 63;
        int m = m0 + r, b = m / Nn, n = m - b * Nn;
        float v = __ldg(&encB[hh]) + nodeEmb[n*Hh + hh];
        #pragma unroll
        for (int f = 0; f < 8; f++) v += sXr[r*8 + f] * sEw[f*64 + hh];
        sXe[hh*65 + r] = v;
    }
    __syncthreads();

    // main: two GEMMs (gx from Xe, gh from H), cols g = gc + 32*j
    int gc = tid & 31, rt = tid >> 5;        // rt: 0..7 -> rows rt*8..rt*8+7
    float accX[8][6], accH[8][6];
    #pragma unroll
    for (int i = 0; i < 8; i++)
        #pragma unroll
        for (int j = 0; j < 6; j++) { accX[i][j] = 0.f; accH[i][j] = 0.f; }

    const float* pXe = sXe + rt*8;
    const float* pH  = sH  + rt*8;
    #pragma unroll 2
    for (int k = 0; k < 64; k++) {
        float ax[8], ah[8];
        #pragma unroll
        for (int i = 0; i < 8; i++) { ax[i] = pXe[k*65 + i]; ah[i] = pH[k*65 + i]; }
        float wx[6], wh[6];
        #pragma unroll
        for (int j = 0; j < 6; j++) {
            wx[j] = sWih[k*193 + gc + 32*j];
            wh[j] = sWhh[k*193 + gc + 32*j];
        }
        #pragma unroll
        for (int i = 0; i < 8; i++)
            #pragma unroll
            for (int j = 0; j < 6; j++) {
                accX[i][j] += ax[i] * wx[j];
                accH[i][j] += ah[i] * wh[j];
            }
    }

    // gates: thread owns (r,z,n) at hidden idx gc and gc+32 for its 8 rows
    #pragma unroll
    for (int i = 0; i < 8; i++) {
        int row = rt*8 + i;
        int m = m0 + row;
        #pragma unroll
        for (int p = 0; p < 2; p++) {
            int idx = gc + 32*p;
            float xr = accX[i][p]     + __ldg(&bih[idx]);
            float hr = accH[i][p]     + __ldg(&bhh[idx]);
            float xz = accX[i][2 + p] + __ldg(&bih[64  + idx]);
            float hz = accH[i][2 + p] + __ldg(&bhh[64  + idx]);
            float xn = accX[i][4 + p] + __ldg(&bih[128 + idx]);
            float hn = accH[i][4 + p] + __ldg(&bhh[128 + idx]);
            float r = 1.f / (1.f + expf(-(xr + hr)));
            float z = 1.f / (1.f + expf(-(xz + hz)));
            float nn = tanhf(xn + r * hn);
            float hp = sH[idx*65 + row];
            hout[m*Hh + idx] = (1.f - z) * nn + z * hp;
        }
    }
}

// ---------------- diffusion propagation (gather over CSR) ----------------
// which: 0: h_final->z0 (fwd), 1: z0->z1 (fwd), 2: h_final->z2 (bwd), 3: z2->z3 (bwd)
__global__ void k_prop(int which) {
    const float* hin; float* out; const int* rowptr; const int* adjn; const float* adjw;
    if (which == 0) { hin = g_h0; out = g_z0; rowptr = g_rowptr_f; adjn = g_adjn_f; adjw = g_adjw_f; }
    else if (which == 1) { hin = g_z0; out = g_z1; rowptr = g_rowptr_f; adjn = g_adjn_f; adjw = g_adjw_f; }
    else if (which == 2) { hin = g_h0; out = g_z2; rowptr = g_rowptr_b; adjn = g_adjn_b; adjw = g_adjw_b; }
    else                 { hin = g_z2; out = g_z3; rowptr = g_rowptr_b; adjn = g_adjn_b; adjw = g_adjw_b; }

    int warp = (blockIdx.x * blockDim.x + threadIdx.x) >> 5;
    int lane = threadIdx.x & 31;
    if (warp >= Nn) return;
    int beg = rowptr[warp], end = rowptr[warp + 1];
    float acc[Bb][2];
    #pragma unroll
    for (int b = 0; b < Bb; b++) { acc[b][0] = 0.f; acc[b][1] = 0.f; }
    for (int e = beg; e < end; e++) {
        int s = adjn[e];
        float w = adjw[e];
        #pragma unroll
        for (int b = 0; b < Bb; b++) {
            const float* hp = hin + (b * Nn + s) * Hh;
            acc[b][0] += hp[lane]      * w;
            acc[b][1] += hp[lane + 32] * w;
        }
    }
    #pragma unroll
    for (int b = 0; b < Bb; b++) {
        float* op = out + (b * Nn + warp) * Hh;
        op[lane]      = acc[b][0];
        op[lane + 32] = acc[b][1];
    }
}

// ---------------- fused filt+dec GEMM + output permute ----------------
#define FIN_SMEM ((KCAT*CDEC + KCAT*65) * 4)

__global__ __launch_bounds__(256, 1)
void k_final(float* __restrict__ out) {
    extern __shared__ float sm[];
    float* sW = sm;                  // [320][96]
    float* sA = sm + KCAT*CDEC;      // [320][65] k-major

    int tid = threadIdx.x;
    int m0  = blockIdx.x * 64;

    for (int idx = tid; idx < KCAT*CDEC; idx += 256) sW[idx] = g_W2[idx];

    const float* srcs[5] = { g_h0, g_z0, g_z1, g_z2, g_z3 };
    #pragma unroll
    for (int a = 0; a < 5; a++) {
        const float* S = srcs[a];
        for (int idx = tid; idx < 64*64; idx += 256) {
            int r = idx >> 6, k = idx & 63;
            sA[(a*64 + k)*65 + r] = S[(m0 + r) * Hh + k];
        }
    }
    __syncthreads();

    int gc = tid & 31, rt = tid >> 5;
    float acc[8][3];
    #pragma unroll
    for (int i = 0; i < 8; i++)
        #pragma unroll
        for (int j = 0; j < 3; j++) acc[i][j] = 0.f;

    #pragma unroll 2
    for (int k = 0; k < KCAT; k++) {
        float av[8];
        #pragma unroll
        for (int i = 0; i < 8; i++) av[i] = sA[k*65 + rt*8 + i];
        float wv[3];
        #pragma unroll
        for (int j = 0; j < 3; j++) wv[j] = sW[k*CDEC + gc + 32*j];
        #pragma unroll
        for (int i = 0; i < 8; i++)
            #pragma unroll
            for (int j = 0; j < 3; j++) acc[i][j] += av[i] * wv[j];
    }

    #pragma unroll
    for (int i = 0; i < 8; i++) {
        int m = m0 + rt*8 + i;
        int b = m / Nn, n = m - b * Nn;
        #pragma unroll
        for (int j = 0; j < 3; j++) {
            int c = gc + 32*j;
            int tt = c >> 3, f = c & 7;
            out[((b * HOR + tt) * Nn + n) * Ff + f] = acc[i][j] + g_b2[c];
        }
    }
}

// ---------------- launch ----------------
extern "C" void kernel_launch(void* const* d_in, const int* in_sizes, int n_in,
                              void* d_out, int out_size) {
    const float* x     = (const float*)d_in[0];
    const void*  ei    = d_in[1];
    const float* ew    = (const float*)d_in[2];
    const float* encW  = (const float*)d_in[3];
    const float* encB  = (const float*)d_in[4];
    const float* nemb  = (const float*)d_in[5];
    const float* Wih   = (const float*)d_in[6];
    const float* Whh   = (const float*)d_in[7];
    const float* bih   = (const float*)d_in[8];
    const float* bhh   = (const float*)d_in[9];
    const float* filtW = (const float*)d_in[10];
    const float* filtB = (const float*)d_in[11];
    const float* decW  = (const float*)d_in[12];
    const float* decB  = (const float*)d_in[13];
    float* out = (float*)d_out;

    cudaFuncSetAttribute(k_gru,   cudaFuncAttributeMaxDynamicSharedMemorySize, GRU_SMEM);
    cudaFuncSetAttribute(k_final, cudaFuncAttributeMaxDynamicSharedMemorySize, FIN_SMEM);

    k_detect<<<1, 1>>>((const unsigned int*)ei);
    k_convert<<<(Ee + 255) / 256, 256>>>(ei);
    k_zero<<<2048, 256>>>();
    k_count<<<(Ee + 255) / 256, 256>>>(ew);
    k_scan<<<1, 1024>>>();
    k_fill<<<(Ee + 255) / 256, 256>>>(ew);
    k_w2<<<KCAT + 1, CDEC>>>(filtW, filtB, decW, decB);

    for (int t = 0; t < Tt; t++)
        k_gru<<<Mm / 64, 256, GRU_SMEM>>>(x, encW, encB, nemb, Wih, Whh, bih, bhh, t);

    k_prop<<<(Nn * 32 + 255) / 256, 256>>>(0);
    k_prop<<<(Nn * 32 + 255) / 256, 256>>>(1);
    k_prop<<<(Nn * 32 + 255) / 256, 256>>>(2);
    k_prop<<<(Nn * 32 + 255) / 256, 256>>>(3);

    k_final<<<Mm / 64, 256, FIN_SMEM>>>(out);
}

// round 3
// speedup vs baseline: 1.5149x; 1.5149x over previous
#include <cuda_runtime.h>
#include <cuda_fp16.h>
#include <math.h>
#include <stdint.h>

// ---------------- problem constants ----------------
#define Nn   10000
#define Bb   8
#define Tt   12
#define Ff   8
#define Hh   64
#define Ee   320000
#define HOR  12
#define Mm   (Bb*Nn)          // 80000 rows
#define KCAT 320              // 5*H
#define CDEC 96               // F*HOR

// ---------------- scratch (__device__ globals; no cudaMalloc) ----------------
__device__ float g_h0[Mm*Hh];
__device__ float g_h1[Mm*Hh];
__device__ float g_z0[Mm*Hh];
__device__ float g_z1[Mm*Hh];
__device__ float g_z2[Mm*Hh];
__device__ float g_z3[Mm*Hh];
__device__ int   g_src[Ee], g_tgt[Ee];
__device__ int   g_rowptr_f[Nn+1], g_rowptr_b[Nn+1];
__device__ int   g_cnt_f[Nn], g_cnt_b[Nn], g_cur_f[Nn], g_cur_b[Nn];
__device__ float g_deg_f[Nn], g_deg_b[Nn];
__device__ int   g_adjn_f[Ee]; __device__ float g_adjw_f[Ee];
__device__ int   g_adjn_b[Ee]; __device__ float g_adjw_b[Ee];
__device__ float g_W2[KCAT*CDEC];
__device__ float g_b2[CDEC];
__device__ int   g_flag64;

// hi/lo fp16 weight image, padded N-major layout.
// Per precision (26624 halves): BT1[128n][136k] (17408), BT2a[64n][72k] (4608), BT2b[64n][72k] (4608)
#define BT1_H  17408
#define BT2A_H 17408
#define BT2B_H 22016
#define BPREC_H 26624
__device__ __half g_Bimg[2*BPREC_H];

// ---------------- mma helpers (base-PTX, no 'a'-arch features) ----------------
__device__ __forceinline__ uint32_t smem_u32(const void* p) {
    uint32_t a;
    asm("{ .reg .u64 t; cvta.to.shared.u64 t, %1; cvt.u32.u64 %0, t; }" : "=r"(a) : "l"(p));
    return a;
}
__device__ __forceinline__ void ldmat4(uint32_t* f, uint32_t addr) {
    asm volatile("ldmatrix.sync.aligned.m8n8.x4.shared.b16 {%0,%1,%2,%3}, [%4];"
        : "=r"(f[0]), "=r"(f[1]), "=r"(f[2]), "=r"(f[3]) : "r"(addr));
}
__device__ __forceinline__ void mma16816(float* c, const uint32_t* a, uint32_t b0, uint32_t b1) {
    asm volatile("mma.sync.aligned.m16n8k16.row.col.f32.f16.f16.f32 "
        "{%0,%1,%2,%3}, {%4,%5,%6,%7}, {%8,%9}, {%0,%1,%2,%3};"
        : "+f"(c[0]), "+f"(c[1]), "+f"(c[2]), "+f"(c[3])
        : "r"(a[0]), "r"(a[1]), "r"(a[2]), "r"(a[3]), "r"(b0), "r"(b1));
}

// ---------------- edge dtype detection ----------------
__global__ void k_detect(const unsigned int* ei_raw) {
    bool all0 = true;
    for (int i = 0; i < 16; i++)
        if (ei_raw[2*i + 1] != 0u) all0 = false;
    g_flag64 = all0 ? 1 : 0;
}

__global__ void k_convert(const void* ei) {
    int e = blockIdx.x * blockDim.x + threadIdx.x;
    if (e >= Ee) return;
    if (g_flag64) {
        const long long* p = (const long long*)ei;
        g_src[e] = (int)p[e];
        g_tgt[e] = (int)p[Ee + e];
    } else {
        const int* p = (const int*)ei;
        g_src[e] = p[e];
        g_tgt[e] = p[Ee + e];
    }
}

// ---------------- zero init ----------------
__global__ void k_zero() {
    int stride = gridDim.x * blockDim.x;
    for (int i = blockIdx.x * blockDim.x + threadIdx.x; i < Mm*Hh; i += stride) {
        g_h0[i] = 0.f;
        if (i < Nn) {
            g_cnt_f[i] = 0; g_cnt_b[i] = 0;
            g_cur_f[i] = 0; g_cur_b[i] = 0;
            g_deg_f[i] = 0.f; g_deg_b[i] = 0.f;
        }
    }
}

// ---------------- CSR build ----------------
__global__ void k_count(const float* __restrict__ ew) {
    int e = blockIdx.x * blockDim.x + threadIdx.x;
    if (e >= Ee) return;
    int s = g_src[e], t = g_tgt[e];
    float w = ew[e];
    atomicAdd(&g_cnt_f[t], 1);  atomicAdd(&g_deg_f[t], w);
    atomicAdd(&g_cnt_b[s], 1);  atomicAdd(&g_deg_b[s], w);
}

__global__ void k_scan() {
    __shared__ int sbuf[1024];
    __shared__ int sOff;
    int tid = threadIdx.x;
    for (int which = 0; which < 2; ++which) {
        const int* cnt = which ? g_cnt_b : g_cnt_f;
        int* rp        = which ? g_rowptr_b : g_rowptr_f;
        if (tid == 0) { sOff = 0; rp[0] = 0; }
        __syncthreads();
        for (int base = 0; base < Nn; base += 1024) {
            int i = base + tid;
            int v = (i < Nn) ? cnt[i] : 0;
            sbuf[tid] = v;
            __syncthreads();
            for (int d = 1; d < 1024; d <<= 1) {
                int add = (tid >= d) ? sbuf[tid - d] : 0;
                __syncthreads();
                sbuf[tid] += add;
                __syncthreads();
            }
            if (i < Nn) rp[i + 1] = sOff + sbuf[tid];
            __syncthreads();
            if (tid == 0) sOff += sbuf[1023];
            __syncthreads();
        }
        __syncthreads();
    }
}

__global__ void k_fill(const float* __restrict__ ew) {
    int e = blockIdx.x * blockDim.x + threadIdx.x;
    if (e >= Ee) return;
    int s = g_src[e], t = g_tgt[e];
    float w = ew[e];
    float df = g_deg_f[t]; df = (df == 0.f) ? 1.f : df;
    int pf = g_rowptr_f[t] + atomicAdd(&g_cur_f[t], 1);
    g_adjn_f[pf] = s;  g_adjw_f[pf] = w / df;
    float db = g_deg_b[s]; db = (db == 0.f) ? 1.f : db;
    int pb = g_rowptr_b[s] + atomicAdd(&g_cur_b[s], 1);
    g_adjn_b[pb] = t;  g_adjw_b[pb] = w / db;
}

// ---------------- W2 = filt_W @ dec_W ; b2 = filt_b @ dec_W + dec_b ----------------
__global__ void k_w2(const float* __restrict__ filtW, const float* __restrict__ filtB,
                     const float* __restrict__ decW,  const float* __restrict__ decB) {
    int c = threadIdx.x;
    int k = blockIdx.x;
    if (k < KCAT) {
        float acc = 0.f;
        for (int j = 0; j < Hh; j++) acc += filtW[k*Hh + j] * decW[j*CDEC + c];
        g_W2[k*CDEC + c] = acc;
    } else {
        float acc = decB[c];
        for (int j = 0; j < Hh; j++) acc += filtB[j] * decW[j*CDEC + c];
        g_b2[c] = acc;
    }
}

// ---------------- weight hi/lo split into padded N-major image ----------------
// BT1[n][k]: n 0..127 (r rows 0..63, z rows 64..127), k 0..127 (k<64: Wih[n][k], k>=64: Whh[n][k-64])
// BT2a[n][k] = Wih[128+n][k]; BT2b[n][k] = Whh[128+n][k]
__global__ void k_prepw(const float* __restrict__ Wih, const float* __restrict__ Whh) {
    int idx = blockIdx.x * blockDim.x + threadIdx.x;
    if (idx >= 2*BPREC_H) return;
    int prec = idx / BPREC_H;
    int p    = idx % BPREC_H;
    float val = 0.f;
    if (p < BT1_H) {
        int n = p / 136, k = p % 136;
        if (k < 64)       val = Wih[n*Hh + k];
        else if (k < 128) val = Whh[n*Hh + (k - 64)];
    } else if (p < BT2B_H) {
        int q = p - BT2A_H;
        int n = q / 72, k = q % 72;
        if (k < 64) val = Wih[(128 + n)*Hh + k];
    } else {
        int q = p - BT2B_H;
        int n = q / 72, k = q % 72;
        if (k < 64) val = Whh[(128 + n)*Hh + k];
    }
    __half hi = __float2half_rn(val);
    __half lo = __float2half_rn(val - __half2float(hi));
    g_Bimg[idx] = prec ? lo : hi;
}

// ---------------- mma fused encoder + GRU step ----------------
// Block: 128 rows, 512 threads (16 warps = 4M x 4N).
// smem halves: A_hi[128*136] @0, A_lo @17408, B_hi @34816 (+26624 for B_lo)
// smem bytes: A/B = 176128; scratch floats: sXr[1024] @176128B, sEw[512] @180224B.
// Epilogue fp32 buffer sE[128][260] overlays A/B after mma completes.
#define A_LO_HOFF 17408
#define B_HOFF    34816
#define GRUMMA_SMEM (176128 + 6144)

__global__ __launch_bounds__(512, 1)
void k_gru_mma(const float* __restrict__ x,
               const float* __restrict__ encW, const float* __restrict__ encB,
               const float* __restrict__ nodeEmb,
               const float* __restrict__ bih, const float* __restrict__ bhh,
               int t)
{
    extern __shared__ __align__(16) char smraw[];
    __half* smh = (__half*)smraw;
    float* sXr = (float*)(smraw + 176128);   // [128][8]
    float* sEw = sXr + 1024;                 // [8][64]
    float* sE  = (float*)smraw;              // epilogue overlay [128][260]

    const float* hin = (t & 1) ? g_h1 : g_h0;
    float*       hout= (t & 1) ? g_h0 : g_h1;

    int tid  = threadIdx.x;
    int lane = tid & 31;
    int wid  = tid >> 5;          // 0..15
    int mw   = wid & 3;           // M-warp
    int nw   = wid >> 2;          // N-warp
    int m0   = blockIdx.x * 128;

    // ---- stage x rows, encoder weights; copy both B images ----
    for (int i = tid; i < 1024; i += 512) {
        int r = i >> 3, f = i & 7;
        int m = m0 + r, b = m / Nn, n = m - b * Nn;
        sXr[i] = x[((b * Tt + t) * Nn + n) * Ff + f];
    }
    if (tid < 512) sEw[tid] = encW[tid];
    {
        const uint4* src = (const uint4*)g_Bimg;
        uint4* dst = (uint4*)(smh + B_HOFF);
        for (int i = tid; i < (2*BPREC_H*2)/16; i += 512) dst[i] = src[i];
    }
    __syncthreads();

    // ---- A fill: Xe (cols 0..63) and H (cols 64..127), hi/lo split ----
    {
        int r  = tid >> 2;
        int kq = (tid & 3) * 16;
        int m = m0 + r, b = m / Nn, n = m - b * Nn;
        float xv[8];
        #pragma unroll
        for (int f = 0; f < 8; f++) xv[f] = sXr[r*8 + f];

        __half* dHi = smh + r*136 + kq;
        __half* dLo = dHi + A_LO_HOFF;
        #pragma unroll
        for (int j = 0; j < 16; j += 2) {
            int k = kq + j;
            float v0 = __ldg(&encB[k])   + __ldg(&nodeEmb[n*Hh + k]);
            float v1 = __ldg(&encB[k+1]) + __ldg(&nodeEmb[n*Hh + k + 1]);
            #pragma unroll
            for (int f = 0; f < 8; f++) {
                v0 += xv[f] * sEw[f*64 + k];
                v1 += xv[f] * sEw[f*64 + k + 1];
            }
            __half h0 = __float2half_rn(v0), h1 = __float2half_rn(v1);
            __half l0 = __float2half_rn(v0 - __half2float(h0));
            __half l1 = __float2half_rn(v1 - __half2float(h1));
            *(__half2*)(dHi + j) = __halves2half2(h0, h1);
            *(__half2*)(dLo + j) = __halves2half2(l0, l1);
        }
        const float* hp = hin + m*Hh + kq;
        __half* dHiH = smh + r*136 + 64 + kq;
        __half* dLoH = dHiH + A_LO_HOFF;
        #pragma unroll
        for (int j = 0; j < 16; j += 2) {
            float v0 = hp[j], v1 = hp[j+1];
            __half h0 = __float2half_rn(v0), h1 = __float2half_rn(v1);
            __half l0 = __float2half_rn(v0 - __half2float(h0));
            __half l1 = __float2half_rn(v1 - __half2float(h1));
            *(__half2*)(dHiH + j) = __halves2half2(h0, h1);
            *(__half2*)(dLoH + j) = __halves2half2(l0, l1);
        }
    }
    __syncthreads();

    // ---- 3-pass mma: C1 (r,z; K=128) + C2 (xn or hn; K=64) ----
    float acc1[2][4][4];
    float acc2[2][4][4];
    #pragma unroll
    for (int i = 0; i < 2; i++)
        #pragma unroll
        for (int j = 0; j < 4; j++)
            #pragma unroll
            for (int q = 0; q < 4; q++) { acc1[i][j][q] = 0.f; acc2[i][j][q] = 0.f; }

    uint32_t sb = smem_u32(smraw);
    int arow  = lane & 15;
    int acol8 = (lane >> 4) * 8;
    int bn    = lane >> 2;        // n within 8-tile
    int bc2   = 2 * (lane & 3);   // k pair base

    #pragma unroll
    for (int p = 0; p < 3; p++) {
        uint32_t aB = sb + ((p == 1) ? A_LO_HOFF : 0) * 2;
        uint32_t bB = sb + (B_HOFF + ((p == 2) ? BPREC_H : 0)) * 2;
        uint32_t b2B = bB + ((nw < 2) ? BT2A_H : BT2B_H) * 2;

        #pragma unroll
        for (int ks = 0; ks < 8; ks++) {
            uint32_t afr[2][4];
            #pragma unroll
            for (int mt = 0; mt < 2; mt++) {
                int R = mw*32 + mt*16;
                ldmat4(afr[mt], aB + ((R + arow)*136 + ks*16 + acol8) * 2);
            }
            // C1: B = BT1 rows n (stride 136), k = ks*16
            #pragma unroll
            for (int nt = 0; nt < 4; nt++) {
                int n = nw*32 + nt*8 + bn;
                uint32_t bo = bB + (n*136 + ks*16 + bc2) * 2;
                uint32_t b0 = *(const uint32_t*)(smraw + (bo - sb));
                uint32_t b1 = *(const uint32_t*)(smraw + (bo - sb) + 16);
                mma16816(acc1[0][nt], afr[0], b0, b1);
                mma16816(acc1[1][nt], afr[1], b0, b1);
            }
            // C2: nw<2 -> xn over ks 0..3 (Xe cols); nw>=2 -> hn over ks 4..7 (H cols)
            bool act = (nw < 2) ? (ks < 4) : (ks >= 4);
            if (act) {
                int ksl = ks & 3;
                #pragma unroll
                for (int nt = 0; nt < 4; nt++) {
                    int n2 = (nw & 1)*32 + nt*8 + bn;
                    uint32_t bo = b2B + (n2*72 + ksl*16 + bc2) * 2;
                    uint32_t b0 = *(const uint32_t*)(smraw + (bo - sb));
                    uint32_t b1 = *(const uint32_t*)(smraw + (bo - sb) + 16);
                    mma16816(acc2[0][nt], afr[0], b0, b1);
                    mma16816(acc2[1][nt], afr[1], b0, b1);
                }
            }
        }
    }
    __syncthreads();   // all mma done; A/B smem now dead -> reuse as sE

    // ---- write accumulators to sE[128][260]: cols 0..127 rz, 128..191 xn, 192..255 hn ----
    {
        int g  = lane >> 2;
        int c2 = 2 * (lane & 3);
        #pragma unroll
        for (int mt = 0; mt < 2; mt++) {
            int R = mw*32 + mt*16 + g;
            #pragma unroll
            for (int nt = 0; nt < 4; nt++) {
                int col1 = nw*32 + nt*8 + c2;
                *(float2*)&sE[R*260 + col1]       = make_float2(acc1[mt][nt][0], acc1[mt][nt][1]);
                *(float2*)&sE[(R+8)*260 + col1]   = make_float2(acc1[mt][nt][2], acc1[mt][nt][3]);
                int col2 = 128 + ((nw >= 2) ? 64 : 0) + (nw & 1)*32 + nt*8 + c2;
                *(float2*)&sE[R*260 + col2]       = make_float2(acc2[mt][nt][0], acc2[mt][nt][1]);
                *(float2*)&sE[(R+8)*260 + col2]   = make_float2(acc2[mt][nt][2], acc2[mt][nt][3]);
            }
        }
    }
    __syncthreads();

    // ---- gates + output ----
    {
        int r  = tid >> 2;
        int jq = (tid & 3) * 16;
        int m  = m0 + r;
        const float* hp = hin + m*Hh;
        float ov[16];
        #pragma unroll
        for (int jj = 0; jj < 16; jj++) {
            int j = jq + jj;
            float rv  = sE[r*260 + j]        + __ldg(&bih[j])      + __ldg(&bhh[j]);
            float zv  = sE[r*260 + 64 + j]   + __ldg(&bih[64+j])   + __ldg(&bhh[64+j]);
            float xnv = sE[r*260 + 128 + j]  + __ldg(&bih[128+j]);
            float hnv = sE[r*260 + 192 + j]  + __ldg(&bhh[128+j]);
            float rg = 1.f / (1.f + expf(-rv));
            float zg = 1.f / (1.f + expf(-zv));
            float ng = tanhf(xnv + rg * hnv);
            ov[jj] = (1.f - zg) * ng + zg * hp[j];
        }
        float4* o4 = (float4*)(hout + m*Hh + jq);
        #pragma unroll
        for (int q = 0; q < 4; q++)
            o4[q] = make_float4(ov[q*4], ov[q*4+1], ov[q*4+2], ov[q*4+3]);
    }
}

// ---------------- diffusion propagation (gather over CSR) ----------------
__global__ void k_prop(int which) {
    const float* hin; float* out; const int* rowptr; const int* adjn; const float* adjw;
    if (which == 0) { hin = g_h0; out = g_z0; rowptr = g_rowptr_f; adjn = g_adjn_f; adjw = g_adjw_f; }
    else if (which == 1) { hin = g_z0; out = g_z1; rowptr = g_rowptr_f; adjn = g_adjn_f; adjw = g_adjw_f; }
    else if (which == 2) { hin = g_h0; out = g_z2; rowptr = g_rowptr_b; adjn = g_adjn_b; adjw = g_adjw_b; }
    else                 { hin = g_z2; out = g_z3; rowptr = g_rowptr_b; adjn = g_adjn_b; adjw = g_adjw_b; }

    int warp = (blockIdx.x * blockDim.x + threadIdx.x) >> 5;
    int lane = threadIdx.x & 31;
    if (warp >= Nn) return;
    int beg = rowptr[warp], end = rowptr[warp + 1];
    float acc[Bb][2];
    #pragma unroll
    for (int b = 0; b < Bb; b++) { acc[b][0] = 0.f; acc[b][1] = 0.f; }
    for (int e = beg; e < end; e++) {
        int s = adjn[e];
        float w = adjw[e];
        #pragma unroll
        for (int b = 0; b < Bb; b++) {
            const float* hp = hin + (b * Nn + s) * Hh;
            acc[b][0] += hp[lane]      * w;
            acc[b][1] += hp[lane + 32] * w;
        }
    }
    #pragma unroll
    for (int b = 0; b < Bb; b++) {
        float* op = out + (b * Nn + warp) * Hh;
        op[lane]      = acc[b][0];
        op[lane + 32] = acc[b][1];
    }
}

// ---------------- fused filt+dec GEMM + output permute ----------------
#define FIN_SMEM ((KCAT*CDEC + KCAT*65) * 4)

__global__ __launch_bounds__(256, 1)
void k_final(float* __restrict__ out) {
    extern __shared__ float smf[];
    float* sW = smf;
    float* sA = smf + KCAT*CDEC;

    int tid = threadIdx.x;
    int m0  = blockIdx.x * 64;

    for (int idx = tid; idx < KCAT*CDEC; idx += 256) sW[idx] = g_W2[idx];

    const float* srcs[5] = { g_h0, g_z0, g_z1, g_z2, g_z3 };
    #pragma unroll
    for (int a = 0; a < 5; a++) {
        const float* S = srcs[a];
        for (int idx = tid; idx < 64*64; idx += 256) {
            int r = idx >> 6, k = idx & 63;
            sA[(a*64 + k)*65 + r] = S[(m0 + r) * Hh + k];
        }
    }
    __syncthreads();

    int gc = tid & 31, rt = tid >> 5;
    float acc[8][3];
    #pragma unroll
    for (int i = 0; i < 8; i++)
        #pragma unroll
        for (int j = 0; j < 3; j++) acc[i][j] = 0.f;

    #pragma unroll 2
    for (int k = 0; k < KCAT; k++) {
        float av[8];
        #pragma unroll
        for (int i = 0; i < 8; i++) av[i] = sA[k*65 + rt*8 + i];
        float wv[3];
        #pragma unroll
        for (int j = 0; j < 3; j++) wv[j] = sW[k*CDEC + gc + 32*j];
        #pragma unroll
        for (int i = 0; i < 8; i++)
            #pragma unroll
            for (int j = 0; j < 3; j++) acc[i][j] += av[i] * wv[j];
    }

    #pragma unroll
    for (int i = 0; i < 8; i++) {
        int m = m0 + rt*8 + i;
        int b = m / Nn, n = m - b * Nn;
        #pragma unroll
        for (int j = 0; j < 3; j++) {
            int c = gc + 32*j;
            int tt = c >> 3, f = c & 7;
            out[((b * HOR + tt) * Nn + n) * Ff + f] = acc[i][j] + g_b2[c];
        }
    }
}

// ---------------- launch ----------------
extern "C" void kernel_launch(void* const* d_in, const int* in_sizes, int n_in,
                              void* d_out, int out_size) {
    const float* x     = (const float*)d_in[0];
    const void*  ei    = d_in[1];
    const float* ew    = (const float*)d_in[2];
    const float* encW  = (const float*)d_in[3];
    const float* encB  = (const float*)d_in[4];
    const float* nemb  = (const float*)d_in[5];
    const float* Wih   = (const float*)d_in[6];
    const float* Whh   = (const float*)d_in[7];
    const float* bih   = (const float*)d_in[8];
    const float* bhh   = (const float*)d_in[9];
    const float* filtW = (const float*)d_in[10];
    const float* filtB = (const float*)d_in[11];
    const float* decW  = (const float*)d_in[12];
    const float* decB  = (const float*)d_in[13];
    float* out = (float*)d_out;

    cudaFuncSetAttribute(k_gru_mma, cudaFuncAttributeMaxDynamicSharedMemorySize, GRUMMA_SMEM);
    cudaFuncSetAttribute(k_final,   cudaFuncAttributeMaxDynamicSharedMemorySize, FIN_SMEM);

    k_detect<<<1, 1>>>((const unsigned int*)ei);
    k_convert<<<(Ee + 255) / 256, 256>>>(ei);
    k_zero<<<2048, 256>>>();
    k_count<<<(Ee + 255) / 256, 256>>>(ew);
    k_scan<<<1, 1024>>>();
    k_fill<<<(Ee + 255) / 256, 256>>>(ew);
    k_w2<<<KCAT + 1, CDEC>>>(filtW, filtB, decW, decB);
    k_prepw<<<(2*BPREC_H + 255) / 256, 256>>>(Wih, Whh);

    for (int t = 0; t < Tt; t++)
        k_gru_mma<<<Mm / 128, 512, GRUMMA_SMEM>>>(x, encW, encB, nemb, bih, bhh, t);

    k_prop<<<(Nn * 32 + 255) / 256, 256>>>(0);
    k_prop<<<(Nn * 32 + 255) / 256, 256>>>(1);
    k_prop<<<(Nn * 32 + 255) / 256, 256>>>(2);
    k_prop<<<(Nn * 32 + 255) / 256, 256>>>(3);

    k_final<<<Mm / 64, 256, FIN_SMEM>>>(out);
}

// round 4
// speedup vs baseline: 2.1278x; 1.4046x over previous
#include <cuda_runtime.h>
#include <cuda_fp16.h>
#include <math.h>
#include <stdint.h>

// ---------------- problem constants ----------------
#define Nn   10000
#define Bb   8
#define Tt   12
#define Ff   8
#define Hh   64
#define Ee   320000
#define HOR  12
#define Mm   (Bb*Nn)          // 80000 rows
#define KCAT 320              // 5*H
#define CDEC 96               // F*HOR

// ---------------- scratch (__device__ globals; no cudaMalloc) ----------------
__device__ float g_h0[Mm*Hh];
__device__ float g_z0[Mm*Hh];
__device__ float g_z1[Mm*Hh];
__device__ float g_z2[Mm*Hh];
__device__ float g_z3[Mm*Hh];
__device__ int   g_src[Ee], g_tgt[Ee];
__device__ int   g_rowptr_f[Nn+1], g_rowptr_b[Nn+1];
__device__ int   g_cnt_f[Nn], g_cnt_b[Nn], g_cur_f[Nn], g_cur_b[Nn];
__device__ float g_deg_f[Nn], g_deg_b[Nn];
__device__ int   g_adjn_f[Ee]; __device__ float g_adjw_f[Ee];
__device__ int   g_adjn_b[Ee]; __device__ float g_adjw_b[Ee];
__device__ float g_W2[KCAT*CDEC];
__device__ float g_b2[CDEC];
__device__ int   g_flag64;

// hi/lo fp16 weight image, padded N-major layout.
// Per precision (26624 halves): BT1[128n][136k], BT2a[64n][72k] @17408, BT2b[64n][72k] @22016
#define BT1_H   17408
#define BT2A_H  17408
#define BT2B_H  22016
#define BPREC_H 26624
__device__ __half g_Bimg[2*BPREC_H];

// ---------------- mma helpers (base-PTX only) ----------------
__device__ __forceinline__ uint32_t smem_u32(const void* p) {
    uint32_t a;
    asm("{ .reg .u64 t; cvta.to.shared.u64 t, %1; cvt.u32.u64 %0, t; }" : "=r"(a) : "l"(p));
    return a;
}
__device__ __forceinline__ void ldmat4(uint32_t* f, uint32_t addr) {
    asm volatile("ldmatrix.sync.aligned.m8n8.x4.shared.b16 {%0,%1,%2,%3}, [%4];"
        : "=r"(f[0]), "=r"(f[1]), "=r"(f[2]), "=r"(f[3]) : "r"(addr));
}
__device__ __forceinline__ void mma16816(float* c, const uint32_t* a, uint32_t b0, uint32_t b1) {
    asm volatile("mma.sync.aligned.m16n8k16.row.col.f32.f16.f16.f32 "
        "{%0,%1,%2,%3}, {%4,%5,%6,%7}, {%8,%9}, {%0,%1,%2,%3};"
        : "+f"(c[0]), "+f"(c[1]), "+f"(c[2]), "+f"(c[3])
        : "r"(a[0]), "r"(a[1]), "r"(a[2]), "r"(a[3]), "r"(b0), "r"(b1));
}

// ---------------- edge dtype detection & conversion ----------------
__global__ void k_detect(const unsigned int* ei_raw) {
    bool all0 = true;
    for (int i = 0; i < 16; i++)
        if (ei_raw[2*i + 1] != 0u) all0 = false;
    g_flag64 = all0 ? 1 : 0;
}

__global__ void k_convert(const void* ei) {
    int e = blockIdx.x * blockDim.x + threadIdx.x;
    if (e >= Ee) return;
    if (g_flag64) {
        const long long* p = (const long long*)ei;
        g_src[e] = (int)p[e];
        g_tgt[e] = (int)p[Ee + e];
    } else {
        const int* p = (const int*)ei;
        g_src[e] = p[e];
        g_tgt[e] = p[Ee + e];
    }
}

// ---------------- zero init (per-node arrays only; h lives in smem now) ----------------
__global__ void k_zero() {
    int i = blockIdx.x * blockDim.x + threadIdx.x;
    if (i < Nn) {
        g_cnt_f[i] = 0; g_cnt_b[i] = 0;
        g_cur_f[i] = 0; g_cur_b[i] = 0;
        g_deg_f[i] = 0.f; g_deg_b[i] = 0.f;
    }
}

// ---------------- W2 = filt_W @ dec_W ; b2 = filt_b @ dec_W + dec_b ----------------
__global__ void k_w2(const float* __restrict__ filtW, const float* __restrict__ filtB,
                     const float* __restrict__ decW,  const float* __restrict__ decB) {
    int c = threadIdx.x;
    int k = blockIdx.x;
    if (k < KCAT) {
        float acc = 0.f;
        for (int j = 0; j < Hh; j++) acc += filtW[k*Hh + j] * decW[j*CDEC + c];
        g_W2[k*CDEC + c] = acc;
    } else {
        float acc = decB[c];
        for (int j = 0; j < Hh; j++) acc += filtB[j] * decW[j*CDEC + c];
        g_b2[c] = acc;
    }
}

// ---------------- weight hi/lo split into padded N-major image ----------------
__global__ void k_prepw(const float* __restrict__ Wih, const float* __restrict__ Whh) {
    int idx = blockIdx.x * blockDim.x + threadIdx.x;
    if (idx >= 2*BPREC_H) return;
    int prec = idx / BPREC_H;
    int p    = idx % BPREC_H;
    float val = 0.f;
    if (p < BT1_H) {
        int n = p / 136, k = p % 136;
        if (k < 64)       val = Wih[n*Hh + k];
        else if (k < 128) val = Whh[n*Hh + (k - 64)];
    } else if (p < BT2B_H) {
        int q = p - BT2A_H;
        int n = q / 72, k = q % 72;
        if (k < 64) val = Wih[(128 + n)*Hh + k];
    } else {
        int q = p - BT2B_H;
        int n = q / 72, k = q % 72;
        if (k < 64) val = Whh[(128 + n)*Hh + k];
    }
    __half hi = __float2half_rn(val);
    __half lo = __float2half_rn(val - __half2float(hi));
    g_Bimg[idx] = prec ? lo : hi;
}

// ---------------- fused 12-step encoder+GRU (time loop inside; h in smem) ----------------
// Block = 128 rows, 512 threads (16 warps: 4M x 4N). GRU recurrence is row-local.
// smem map (bytes):
//   0       A_hi [128][136] halves (34816)   <- overlaid by fp32 sE[128][132] during epilogue
//   34816   A_lo (34816)
//   69632   B images hi+lo (106496) — loaded ONCE, live across all 12 steps
//   176128  sH fp32 [128][64] (32768) — hidden state, resident across steps
//   208896  sEw [8][64] fp32 (2048)
//   210944  sXr [128][8] fp32 (4096)
//   215040  sBias [384] fp32 (1536)
#define A_LO_HOFF 17408
#define SM_ALO_B  34816
#define SM_B_B    69632
#define SM_H_B    176128
#define SM_EW_B   208896
#define SM_XR_B   210944
#define SM_BIAS_B 215040
#define GRU_SMEM_B (215040 + 1536)

__global__ __launch_bounds__(512, 1)
void k_gru_fused(const float* __restrict__ x,
                 const float* __restrict__ encW, const float* __restrict__ encB,
                 const float* __restrict__ nodeEmb,
                 const float* __restrict__ bih, const float* __restrict__ bhh)
{
    extern __shared__ __align__(16) char smraw[];
    __half* smh  = (__half*)smraw;
    float* sH    = (float*)(smraw + SM_H_B);
    float* sEw   = (float*)(smraw + SM_EW_B);
    float* sXr   = (float*)(smraw + SM_XR_B);
    float* sBias = (float*)(smraw + SM_BIAS_B);
    float* sE    = (float*)smraw;   // epilogue overlay on A region

    int tid  = threadIdx.x;
    int lane = tid & 31;
    int wid  = tid >> 5;
    int mw   = wid & 3;
    int nw   = wid >> 2;
    int m0   = blockIdx.x * 128;

    // one-time loads: B image (hi+lo), encoder weights, biases; zero h
    {
        const uint4* src = (const uint4*)g_Bimg;
        uint4* dst = (uint4*)(smraw + SM_B_B);
        for (int i = tid; i < (2*BPREC_H*2)/16; i += 512) dst[i] = src[i];
    }
    sEw[tid] = encW[tid];
    if (tid < 192) { sBias[tid] = bih[tid]; sBias[192 + tid] = bhh[tid]; }
    {
        float4* h4 = (float4*)sH;
        for (int i = tid; i < 128*64/4; i += 512) h4[i] = make_float4(0.f,0.f,0.f,0.f);
    }

    // per-thread (row, col-quarter) ownership — identical mapping in A-build & epilogue
    int r  = tid >> 2;
    int kq = (tid & 3) * 16;
    int m  = m0 + r, bq = m / Nn, nq = m - bq * Nn;

    float emb[16];
    #pragma unroll
    for (int j = 0; j < 16; j++)
        emb[j] = __ldg(&encB[kq + j]) + __ldg(&nodeEmb[nq*Hh + kq + j]);

    __syncthreads();

    uint32_t sb = smem_u32(smraw);
    int arow  = lane & 15;
    int acol8 = (lane >> 4) * 8;
    int bn    = lane >> 2;
    int bc2   = 2 * (lane & 3);

    for (int t = 0; t < Tt; t++) {
        // ---- stage x rows for this step (contiguous 8 floats per row) ----
        {
            int rr = tid >> 2, fp = (tid & 3) * 2;
            int mm = m0 + rr, b2 = mm / Nn, n2 = mm - b2 * Nn;
            *(float2*)&sXr[rr*8 + fp] =
                *(const float2*)&x[(((size_t)b2*Tt + t)*Nn + n2)*Ff + fp];
        }
        __syncthreads();

        // ---- A build: Xe (cols 0..63) and H (cols 64..127), hi/lo split ----
        {
            float xv[8];
            #pragma unroll
            for (int f = 0; f < 8; f++) xv[f] = sXr[r*8 + f];

            __half* dHi = smh + r*136 + kq;
            __half* dLo = dHi + A_LO_HOFF;
            #pragma unroll
            for (int j = 0; j < 16; j += 2) {
                int k = kq + j;
                float v0 = emb[j], v1 = emb[j+1];
                #pragma unroll
                for (int f = 0; f < 8; f++) {
                    v0 += xv[f] * sEw[f*64 + k];
                    v1 += xv[f] * sEw[f*64 + k + 1];
                }
                __half h0 = __float2half_rn(v0), h1 = __float2half_rn(v1);
                __half l0 = __float2half_rn(v0 - __half2float(h0));
                __half l1 = __float2half_rn(v1 - __half2float(h1));
                *(__half2*)(dHi + j) = __halves2half2(h0, h1);
                *(__half2*)(dLo + j) = __halves2half2(l0, l1);
            }
            const float* hp = sH + r*64 + kq;
            __half* dHiH = smh + r*136 + 64 + kq;
            __half* dLoH = dHiH + A_LO_HOFF;
            #pragma unroll
            for (int j = 0; j < 16; j += 2) {
                float v0 = hp[j], v1 = hp[j+1];
                __half h0 = __float2half_rn(v0), h1 = __float2half_rn(v1);
                __half l0 = __float2half_rn(v0 - __half2float(h0));
                __half l1 = __float2half_rn(v1 - __half2float(h1));
                *(__half2*)(dHiH + j) = __halves2half2(h0, h1);
                *(__half2*)(dLoH + j) = __halves2half2(l0, l1);
            }
        }
        __syncthreads();

        // ---- 3-pass hi/lo mma: C1 (r,z; K=128) + C2 (xn or hn; K=64) ----
        float acc1[2][4][4];
        float acc2[2][4][4];
        #pragma unroll
        for (int i = 0; i < 2; i++)
            #pragma unroll
            for (int j = 0; j < 4; j++)
                #pragma unroll
                for (int q = 0; q < 4; q++) { acc1[i][j][q] = 0.f; acc2[i][j][q] = 0.f; }

        for (int p = 0; p < 3; p++) {
            uint32_t aB  = sb + ((p == 1) ? SM_ALO_B : 0);
            uint32_t bB  = sb + SM_B_B + ((p == 2) ? BPREC_H*2 : 0);
            uint32_t b2B = bB + ((nw < 2) ? BT2A_H : BT2B_H) * 2;

            #pragma unroll
            for (int ks = 0; ks < 8; ks++) {
                uint32_t afr[2][4];
                #pragma unroll
                for (int mt = 0; mt < 2; mt++) {
                    int R = mw*32 + mt*16;
                    ldmat4(afr[mt], aB + ((R + arow)*136 + ks*16 + acol8) * 2);
                }
                #pragma unroll
                for (int nt = 0; nt < 4; nt++) {
                    int n = nw*32 + nt*8 + bn;
                    uint32_t bo = (bB - sb) + (n*136 + ks*16 + bc2) * 2;
                    uint32_t b0 = *(const uint32_t*)(smraw + bo);
                    uint32_t b1 = *(const uint32_t*)(smraw + bo + 16);
                    mma16816(acc1[0][nt], afr[0], b0, b1);
                    mma16816(acc1[1][nt], afr[1], b0, b1);
                }
                bool act = (nw < 2) ? (ks < 4) : (ks >= 4);
                if (act) {
                    int ksl = ks & 3;
                    #pragma unroll
                    for (int nt = 0; nt < 4; nt++) {
                        int n2 = (nw & 1)*32 + nt*8 + bn;
                        uint32_t bo = (b2B - sb) + (n2*72 + ksl*16 + bc2) * 2;
                        uint32_t b0 = *(const uint32_t*)(smraw + bo);
                        uint32_t b1 = *(const uint32_t*)(smraw + bo + 16);
                        mma16816(acc2[0][nt], afr[0], b0, b1);
                        mma16816(acc2[1][nt], afr[1], b0, b1);
                    }
                }
            }
        }
        __syncthreads();   // A region dead; stage epilogue there

        // ---- stage 1: rz (cols 0..127) into sE[128][132] ----
        {
            int g = lane >> 2, c2 = 2 * (lane & 3);
            #pragma unroll
            for (int mt = 0; mt < 2; mt++) {
                int R = mw*32 + mt*16 + g;
                #pragma unroll
                for (int nt = 0; nt < 4; nt++) {
                    int col = nw*32 + nt*8 + c2;
                    *(float2*)&sE[R*132 + col]     = make_float2(acc1[mt][nt][0], acc1[mt][nt][1]);
                    *(float2*)&sE[(R+8)*132 + col] = make_float2(acc1[mt][nt][2], acc1[mt][nt][3]);
                }
            }
        }
        __syncthreads();
        float rv[16], zv[16];
        #pragma unroll
        for (int jj = 0; jj < 16; jj++) {
            rv[jj] = sE[r*132 + kq + jj];
            zv[jj] = sE[r*132 + 64 + kq + jj];
        }
        __syncthreads();

        // ---- stage 2: xn (cols 0..63) + hn (cols 64..127) ----
        {
            int g = lane >> 2, c2 = 2 * (lane & 3);
            #pragma unroll
            for (int mt = 0; mt < 2; mt++) {
                int R = mw*32 + mt*16 + g;
                #pragma unroll
                for (int nt = 0; nt < 4; nt++) {
                    int col = ((nw >= 2) ? 64 : 0) + (nw & 1)*32 + nt*8 + c2;
                    *(float2*)&sE[R*132 + col]     = make_float2(acc2[mt][nt][0], acc2[mt][nt][1]);
                    *(float2*)&sE[(R+8)*132 + col] = make_float2(acc2[mt][nt][2], acc2[mt][nt][3]);
                }
            }
        }
        __syncthreads();

        // ---- gates: thread owns sH[r][kq..kq+15] exclusively ----
        {
            float ov[16];
            #pragma unroll
            for (int jj = 0; jj < 16; jj++) {
                int j = kq + jj;
                float xnv = sE[r*132 + j]      + sBias[128 + j];
                float hnv = sE[r*132 + 64 + j] + sBias[192 + 128 + j];
                float rvv = rv[jj] + sBias[j]      + sBias[192 + j];
                float zvv = zv[jj] + sBias[64 + j] + sBias[192 + 64 + j];
                float rg = 1.f / (1.f + expf(-rvv));
                float zg = 1.f / (1.f + expf(-zvv));
                float ng = tanhf(xnv + rg * hnv);
                ov[jj] = (1.f - zg) * ng + zg * sH[r*64 + j];
            }
            #pragma unroll
            for (int jj = 0; jj < 16; jj++) sH[r*64 + kq + jj] = ov[jj];
        }
        __syncthreads();
    }

    // ---- write final hidden state ----
    {
        float4* dst = (float4*)(g_h0 + (size_t)(m0 + r)*Hh + kq);
        const float4* srcp = (const float4*)(sH + r*64 + kq);
        #pragma unroll
        for (int q = 0; q < 4; q++) dst[q] = srcp[q];
    }
}

// ---------------- CSR build ----------------
__global__ void k_count(const float* __restrict__ ew) {
    int e = blockIdx.x * blockDim.x + threadIdx.x;
    if (e >= Ee) return;
    int s = g_src[e], t = g_tgt[e];
    float w = ew[e];
    atomicAdd(&g_cnt_f[t], 1);  atomicAdd(&g_deg_f[t], w);
    atomicAdd(&g_cnt_b[s], 1);  atomicAdd(&g_deg_b[s], w);
}

__global__ void k_scan() {
    __shared__ int sbuf[1024];
    __shared__ int sOff;
    int tid = threadIdx.x;
    for (int which = 0; which < 2; ++which) {
        const int* cnt = which ? g_cnt_b : g_cnt_f;
        int* rp        = which ? g_rowptr_b : g_rowptr_f;
        if (tid == 0) { sOff = 0; rp[0] = 0; }
        __syncthreads();
        for (int base = 0; base < Nn; base += 1024) {
            int i = base + tid;
            int v = (i < Nn) ? cnt[i] : 0;
            sbuf[tid] = v;
            __syncthreads();
            for (int d = 1; d < 1024; d <<= 1) {
                int add = (tid >= d) ? sbuf[tid - d] : 0;
                __syncthreads();
                sbuf[tid] += add;
                __syncthreads();
            }
            if (i < Nn) rp[i + 1] = sOff + sbuf[tid];
            __syncthreads();
            if (tid == 0) sOff += sbuf[1023];
            __syncthreads();
        }
        __syncthreads();
    }
}

__global__ void k_fill(const float* __restrict__ ew) {
    int e = blockIdx.x * blockDim.x + threadIdx.x;
    if (e >= Ee) return;
    int s = g_src[e], t = g_tgt[e];
    float w = ew[e];
    float df = g_deg_f[t]; df = (df == 0.f) ? 1.f : df;
    int pf = g_rowptr_f[t] + atomicAdd(&g_cur_f[t], 1);
    g_adjn_f[pf] = s;  g_adjw_f[pf] = w / df;
    float db = g_deg_b[s]; db = (db == 0.f) ? 1.f : db;
    int pb = g_rowptr_b[s] + atomicAdd(&g_cur_b[s], 1);
    g_adjn_b[pb] = t;  g_adjw_b[pb] = w / db;
}

// ---------------- diffusion propagation: hop1 fused (fwd+bwd from h0) ----------------
__device__ __forceinline__ void prop_body(const float* __restrict__ hin,
                                          float* __restrict__ out,
                                          const int* __restrict__ rowptr,
                                          const int* __restrict__ adjn,
                                          const float* __restrict__ adjw,
                                          int node, int lane) {
    int beg = rowptr[node], end = rowptr[node + 1];
    float acc[Bb][2];
    #pragma unroll
    for (int b = 0; b < Bb; b++) { acc[b][0] = 0.f; acc[b][1] = 0.f; }
    for (int e = beg; e < end; e++) {
        int s = adjn[e];
        float w = adjw[e];
        #pragma unroll
        for (int b = 0; b < Bb; b++) {
            const float* hp = hin + ((size_t)b * Nn + s) * Hh;
            acc[b][0] += hp[lane]      * w;
            acc[b][1] += hp[lane + 32] * w;
        }
    }
    #pragma unroll
    for (int b = 0; b < Bb; b++) {
        float* op = out + ((size_t)b * Nn + node) * Hh;
        op[lane]      = acc[b][0];
        op[lane + 32] = acc[b][1];
    }
}

__global__ void k_prop_h1() {
    int gw   = (blockIdx.x * blockDim.x + threadIdx.x) >> 5;
    int lane = threadIdx.x & 31;
    if (gw >= 2*Nn) return;
    if (gw < Nn) prop_body(g_h0, g_z0, g_rowptr_f, g_adjn_f, g_adjw_f, gw, lane);
    else         prop_body(g_h0, g_z2, g_rowptr_b, g_adjn_b, g_adjw_b, gw - Nn, lane);
}

__global__ void k_prop_h2() {
    int gw   = (blockIdx.x * blockDim.x + threadIdx.x) >> 5;
    int lane = threadIdx.x & 31;
    if (gw >= 2*Nn) return;
    if (gw < Nn) prop_body(g_z0, g_z1, g_rowptr_f, g_adjn_f, g_adjw_f, gw, lane);
    else         prop_body(g_z2, g_z3, g_rowptr_b, g_adjn_b, g_adjw_b, gw - Nn, lane);
}

// ---------------- fused filt+dec GEMM + output permute ----------------
#define FIN_SMEM ((KCAT*CDEC + KCAT*65) * 4)

__global__ __launch_bounds__(256, 1)
void k_final(float* __restrict__ out) {
    extern __shared__ float smf[];
    float* sW = smf;
    float* sA = smf + KCAT*CDEC;

    int tid = threadIdx.x;
    int m0  = blockIdx.x * 64;

    for (int idx = tid; idx < KCAT*CDEC; idx += 256) sW[idx] = g_W2[idx];

    const float* srcs[5] = { g_h0, g_z0, g_z1, g_z2, g_z3 };
    #pragma unroll
    for (int a = 0; a < 5; a++) {
        const float* S = srcs[a];
        for (int idx = tid; idx < 64*64; idx += 256) {
            int r = idx >> 6, k = idx & 63;
            sA[(a*64 + k)*65 + r] = S[(size_t)(m0 + r) * Hh + k];
        }
    }
    __syncthreads();

    int gc = tid & 31, rt = tid >> 5;
    float acc[8][3];
    #pragma unroll
    for (int i = 0; i < 8; i++)
        #pragma unroll
        for (int j = 0; j < 3; j++) acc[i][j] = 0.f;

    #pragma unroll 2
    for (int k = 0; k < KCAT; k++) {
        float av[8];
        #pragma unroll
        for (int i = 0; i < 8; i++) av[i] = sA[k*65 + rt*8 + i];
        float wv[3];
        #pragma unroll
        for (int j = 0; j < 3; j++) wv[j] = sW[k*CDEC + gc + 32*j];
        #pragma unroll
        for (int i = 0; i < 8; i++)
            #pragma unroll
            for (int j = 0; j < 3; j++) acc[i][j] += av[i] * wv[j];
    }

    #pragma unroll
    for (int i = 0; i < 8; i++) {
        int m = m0 + rt*8 + i;
        int b = m / Nn, n = m - b * Nn;
        #pragma unroll
        for (int j = 0; j < 3; j++) {
            int c = gc + 32*j;
            int tt = c >> 3, f = c & 7;
            out[(((size_t)b * HOR + tt) * Nn + n) * Ff + f] = acc[i][j] + g_b2[c];
        }
    }
}

// ---------------- launch ----------------
extern "C" void kernel_launch(void* const* d_in, const int* in_sizes, int n_in,
                              void* d_out, int out_size) {
    const float* x     = (const float*)d_in[0];
    const void*  ei    = d_in[1];
    const float* ew    = (const float*)d_in[2];
    const float* encW  = (const float*)d_in[3];
    const float* encB  = (const float*)d_in[4];
    const float* nemb  = (const float*)d_in[5];
    const float* Wih   = (const float*)d_in[6];
    const float* Whh   = (const float*)d_in[7];
    const float* bih   = (const float*)d_in[8];
    const float* bhh   = (const float*)d_in[9];
    const float* filtW = (const float*)d_in[10];
    const float* filtB = (const float*)d_in[11];
    const float* decW  = (const float*)d_in[12];
    const float* decB  = (const float*)d_in[13];
    float* out = (float*)d_out;

    cudaFuncSetAttribute(k_gru_fused, cudaFuncAttributeMaxDynamicSharedMemorySize, GRU_SMEM_B);
    cudaFuncSetAttribute(k_final,     cudaFuncAttributeMaxDynamicSharedMemorySize, FIN_SMEM);

    // launch order chosen so ncu (-s 5 -c 1) captures k_gru_fused at slot 5
    k_detect<<<1, 1>>>((const unsigned int*)ei);                       // 0
    k_convert<<<(Ee + 255) / 256, 256>>>(ei);                          // 1
    k_zero<<<(Nn + 255) / 256, 256>>>();                               // 2
    k_w2<<<KCAT + 1, CDEC>>>(filtW, filtB, decW, decB);                // 3
    k_prepw<<<(2*BPREC_H + 255) / 256, 256>>>(Wih, Whh);               // 4
    k_gru_fused<<<Mm / 128, 512, GRU_SMEM_B>>>(x, encW, encB, nemb, bih, bhh); // 5
    k_count<<<(Ee + 255) / 256, 256>>>(ew);                            // 6
    k_scan<<<1, 1024>>>();                                             // 7
    k_fill<<<(Ee + 255) / 256, 256>>>(ew);                             // 8
    k_prop_h1<<<(2*Nn*32 + 255) / 256, 256>>>();                       // 9
    k_prop_h2<<<(2*Nn*32 + 255) / 256, 256>>>();                       // 10
    k_final<<<Mm / 64, 256, FIN_SMEM>>>(out);                          // 11
}